// round 6
// baseline (speedup 1.0000x reference)
#include <cuda_runtime.h>
#include <cuda_bf16.h>
#include <cstdint>

#define NN 100000
#define EE 1600000
#define FD 128
#define BB 50
#define PP 2000
#define CC 10
#define KINV (1.0f/30.0f)
#define NBLK ((NN + 255) / 256)   // 391

// Scratch (static device globals — no allocation at launch time).
static __device__ float    g_tmp[NN*FD];     // (A@W) * inv[row]  (gather source)
static __device__ float    g_h1[NN*FD];      // relu(layer-1 output)
static __device__ float    g_h2[NN*FD];      // relu(layer-2 output)
static __device__ float    g_inv[NN];        // rsqrt(deg+1)
static __device__ float    g_part[BB*8*FD];  // pooling partials
static __device__ int      g_cnt[NN];
static __device__ int      g_cur[NN];
static __device__ int      g_off[NN];
static __device__ int      g_src[EE];
static __device__ int      g_blksum[NBLK];
static __device__ int      g_blkoff[NBLK];
// Pre-split weights, transposed [n][k], bf16 pairs packed in u32 ([n][64])
static __device__ uint32_t g_Wh[2][128*64];
static __device__ uint32_t g_Wl[2][128*64];

// ---------------- CSR-by-dst construction ----------------

__global__ void k_zero() {
    int i = blockIdx.x*blockDim.x + threadIdx.x;
    if (i < NN) { g_cnt[i] = 0; g_cur[i] = 0; }
}

__global__ void k_hist(const int* __restrict__ ei, int E) {
    int e = blockIdx.x*blockDim.x + threadIdx.x;
    if (e < E) atomicAdd(&g_cnt[ei[E + e]], 1);
}

__global__ void k_scan_block() {
    __shared__ int sh[256];
    int t = threadIdx.x;
    int i = blockIdx.x*256 + t;
    int v = (i < NN) ? g_cnt[i] : 0;
    sh[t] = v;
    __syncthreads();
    #pragma unroll
    for (int d = 1; d < 256; d <<= 1) {
        int x = (t >= d) ? sh[t-d] : 0;
        __syncthreads();
        sh[t] += x;
        __syncthreads();
    }
    if (i < NN) {
        g_off[i] = sh[t] - v;
        g_inv[i] = rsqrtf((float)v + 1.0f);
    }
    if (t == 255) g_blksum[blockIdx.x] = sh[255];
}

__global__ void k_scan_top() {
    __shared__ int sh[512];
    int t = threadIdx.x;
    int v = (t < NBLK) ? g_blksum[t] : 0;
    sh[t] = v;
    __syncthreads();
    #pragma unroll
    for (int d = 1; d < 512; d <<= 1) {
        int x = (t >= d) ? sh[t-d] : 0;
        __syncthreads();
        sh[t] += x;
        __syncthreads();
    }
    if (t < NBLK) g_blkoff[t] = sh[t] - v;
}

__global__ void k_scan_add() {
    int i = blockIdx.x*256 + threadIdx.x;
    if (i < NN) g_off[i] += g_blkoff[blockIdx.x];
}

__global__ void k_fill(const int* __restrict__ ei, int E) {
    int e = blockIdx.x*blockDim.x + threadIdx.x;
    if (e < E) {
        int s = ei[e];
        int d = ei[E + e];
        int pos = g_off[d] + atomicAdd(&g_cur[d], 1);
        g_src[pos] = s;
    }
}

// ---------------- one-time W split: W[k][n] f32 -> [n][k] bf16 hi/lo ----------------

__global__ void k_splitW(const float* __restrict__ W1, const float* __restrict__ W2) {
    int id = blockIdx.x*256 + threadIdx.x;      // 0..16383
    if (id >= 2*128*64) return;
    int mat   = id >> 13;
    int local = id & 8191;
    int n  = local >> 6;
    int kp = local & 63;                        // k-pair index
    const float* W = mat ? W2 : W1;
    float e0 = W[(2*kp+0)*FD + n];
    float e1 = W[(2*kp+1)*FD + n];
    __nv_bfloat162 hb = __float22bfloat162_rn(make_float2(e0, e1));
    float l0 = e0 - __low2float(hb);
    float l1 = e1 - __high2float(hb);
    __nv_bfloat162 lb = __float22bfloat162_rn(make_float2(l0, l1));
    g_Wh[mat][n*64 + kp] = *reinterpret_cast<uint32_t*>(&hb);
    g_Wl[mat][n*64 + kp] = *reinterpret_cast<uint32_t*>(&lb);
}

// ---------------- bf16 3-term split GEMM: tmp' = (A @ W) * inv[row] ----------------

__device__ __forceinline__ void mma_bf16(float* d, const uint32_t* a, const uint32_t* b) {
    asm volatile(
        "mma.sync.aligned.m16n8k16.row.col.f32.bf16.bf16.f32 "
        "{%0,%1,%2,%3}, {%4,%5,%6,%7}, {%8,%9}, {%0,%1,%2,%3};"
        : "+f"(d[0]), "+f"(d[1]), "+f"(d[2]), "+f"(d[3])
        : "r"(a[0]), "r"(a[1]), "r"(a[2]), "r"(a[3]), "r"(b[0]), "r"(b[1]));
}

// Block: 128 rows x 128 cols, 8 warps: warp_m = wid&1, warp_n = wid>>1.
// smem: A/B hi+lo as bf16-pair u32 arrays, pitch 20 u32 (40 bf16) per row
// -> all fragment LDS conflict-free (20*gid + t4 unique mod 32).
template<int LAYER>
__global__ void __launch_bounds__(256)
k_gemm_bf(const float* __restrict__ X) {
    const float*    A  = (LAYER == 1) ? X : (const float*)g_h1;
    const uint32_t* Wh = g_Wh[LAYER-1];
    const uint32_t* Wl = g_Wl[LAYER-1];

    __shared__ uint32_t AsmH[128*20], AsmL[128*20];
    __shared__ uint32_t BsmH[128*20], BsmL[128*20];

    const int tid  = threadIdx.x;
    const int row0 = blockIdx.x * 128;
    const int wid  = tid >> 5;
    const int lane = tid & 31;
    const int gid  = lane >> 2;
    const int t4   = lane & 3;
    const int m0b  = (wid & 1) * 64;
    const int n0b  = (wid >> 1) * 32;

    float acc[4][4][4];
    #pragma unroll
    for (int mt = 0; mt < 4; mt++)
        #pragma unroll
        for (int nt = 0; nt < 4; nt++)
            #pragma unroll
            for (int r = 0; r < 4; r++) acc[mt][nt][r] = 0.f;

    const int a_row  = tid & 127;
    const int a_ko   = (tid >> 7) * 16;        // 16 k-elements each
    const int a_grow = row0 + a_row;
    const int b_n    = tid & 127;
    const int b_half = tid >> 7;

    for (int k0 = 0; k0 < FD; k0 += 32) {
        // --- A chunk: load f32, split to bf16 hi/lo pairs ---
        {
            float e[16];
            if (a_grow < NN) {
                const float* p = A + (size_t)a_grow*FD + k0 + a_ko;
                #pragma unroll
                for (int q = 0; q < 4; q++) {
                    float4 v = *reinterpret_cast<const float4*>(p + q*4);
                    e[q*4+0] = v.x; e[q*4+1] = v.y; e[q*4+2] = v.z; e[q*4+3] = v.w;
                }
            } else {
                #pragma unroll
                for (int q = 0; q < 16; q++) e[q] = 0.f;
            }
            uint32_t* ah = &AsmH[a_row*20 + (a_ko >> 1)];
            uint32_t* al = &AsmL[a_row*20 + (a_ko >> 1)];
            #pragma unroll
            for (int j = 0; j < 8; j++) {
                float e0 = e[2*j], e1 = e[2*j+1];
                __nv_bfloat162 hb = __float22bfloat162_rn(make_float2(e0, e1));
                float l0 = e0 - __low2float(hb);
                float l1 = e1 - __high2float(hb);
                __nv_bfloat162 lb = __float22bfloat162_rn(make_float2(l0, l1));
                ah[j] = *reinterpret_cast<uint32_t*>(&hb);
                al[j] = *reinterpret_cast<uint32_t*>(&lb);
            }
        }
        // --- B chunk: straight u32 copies from pre-split W ---
        {
            int go = b_n*64 + (k0 >> 1) + b_half*8;
            int so = b_n*20 + b_half*8;
            #pragma unroll
            for (int j = 0; j < 8; j++) {
                BsmH[so + j] = Wh[go + j];
                BsmL[so + j] = Wl[go + j];
            }
        }
        __syncthreads();

        #pragma unroll
        for (int ks = 0; ks < 2; ks++) {       // k16 steps, ksu = ks*8
            const int ksu = ks * 8;
            uint32_t bh[4][2], bl[4][2];
            #pragma unroll
            for (int nt = 0; nt < 4; nt++) {
                int o = (n0b + nt*8 + gid)*20 + ksu + t4;
                bh[nt][0] = BsmH[o];  bh[nt][1] = BsmH[o + 4];
                bl[nt][0] = BsmL[o];  bl[nt][1] = BsmL[o + 4];
            }
            #pragma unroll
            for (int mt = 0; mt < 4; mt++) {
                int o = (m0b + mt*16 + gid)*20 + ksu + t4;
                uint32_t ah[4], al[4];
                ah[0] = AsmH[o];        ah[1] = AsmH[o + 160];
                ah[2] = AsmH[o + 4];    ah[3] = AsmH[o + 164];
                al[0] = AsmL[o];        al[1] = AsmL[o + 160];
                al[2] = AsmL[o + 4];    al[3] = AsmL[o + 164];
                #pragma unroll
                for (int nt = 0; nt < 4; nt++) {
                    mma_bf16(acc[mt][nt], ah, bh[nt]);   // hi*hi
                    mma_bf16(acc[mt][nt], al, bh[nt]);   // lo*hi
                    mma_bf16(acc[mt][nt], ah, bl[nt]);   // hi*lo
                }
            }
        }
        __syncthreads();
    }

    // Epilogue: scale rows by inv and store to g_tmp
    #pragma unroll
    for (int mt = 0; mt < 4; mt++) {
        int r0 = row0 + m0b + mt*16 + gid;
        int r1 = r0 + 8;
        float iv0 = (r0 < NN) ? g_inv[r0] : 0.f;
        float iv1 = (r1 < NN) ? g_inv[r1] : 0.f;
        #pragma unroll
        for (int nt = 0; nt < 4; nt++) {
            int c = n0b + nt*8 + t4*2;
            if (r0 < NN) {
                float2 o = make_float2(acc[mt][nt][0]*iv0, acc[mt][nt][1]*iv0);
                *reinterpret_cast<float2*>(g_tmp + (size_t)r0*FD + c) = o;
            }
            if (r1 < NN) {
                float2 o = make_float2(acc[mt][nt][2]*iv1, acc[mt][nt][3]*iv1);
                *reinterpret_cast<float2*>(g_tmp + (size_t)r1*FD + c) = o;
            }
        }
    }
}

// ---------------- CSR gather: one warp per dst node ----------------

template<int LAYER>
__global__ void __launch_bounds__(256)
k_gather(const float* __restrict__ bias) {
    int node = blockIdx.x*8 + (threadIdx.x >> 5);
    if (node >= NN) return;
    float* H = (LAYER == 1) ? g_h1 : g_h2;

    const int lane  = threadIdx.x & 31;
    const int start = g_off[node];
    const int deg   = g_cnt[node];

    float4 acc0 = *reinterpret_cast<const float4*>(g_tmp + (size_t)node*FD + lane*4);
    float4 acc1 = make_float4(0.f, 0.f, 0.f, 0.f);

    for (int base = 0; base < deg; base += 32) {
        int n = deg - base; if (n > 32) n = 32;
        int s = (base + lane < deg) ? g_src[start + base + lane] : 0;
        int j = 0;
        for (; j + 1 < n; j += 2) {
            int s0 = __shfl_sync(0xffffffff, s, j);
            int s1 = __shfl_sync(0xffffffff, s, j+1);
            float4 v0 = *reinterpret_cast<const float4*>(g_tmp + (size_t)s0*FD + lane*4);
            float4 v1 = *reinterpret_cast<const float4*>(g_tmp + (size_t)s1*FD + lane*4);
            acc0.x += v0.x; acc0.y += v0.y; acc0.z += v0.z; acc0.w += v0.w;
            acc1.x += v1.x; acc1.y += v1.y; acc1.z += v1.z; acc1.w += v1.w;
        }
        if (j < n) {
            int s0 = __shfl_sync(0xffffffff, s, j);
            float4 v0 = *reinterpret_cast<const float4*>(g_tmp + (size_t)s0*FD + lane*4);
            acc0.x += v0.x; acc0.y += v0.y; acc0.z += v0.z; acc0.w += v0.w;
        }
    }

    float invd = g_inv[node];
    float4 b4 = *reinterpret_cast<const float4*>(bias + lane*4);
    float4 h;
    h.x = fmaxf(fmaf(acc0.x + acc1.x, invd, b4.x), 0.f);
    h.y = fmaxf(fmaf(acc0.y + acc1.y, invd, b4.y), 0.f);
    h.z = fmaxf(fmaf(acc0.z + acc1.z, invd, b4.z), 0.f);
    h.w = fmaxf(fmaf(acc0.w + acc1.w, invd, b4.w), 0.f);
    *reinterpret_cast<float4*>(H + (size_t)node*FD + lane*4) = h;
}

// ---------------- pooling + final ----------------

__global__ void k_pool() {
    int b = blockIdx.x >> 3;
    int q = blockIdx.x & 7;
    int d = threadIdx.x;
    const float* base = g_h2 + ((size_t)(b*PP + q*(PP/8)))*FD + d;
    float s = 0.f;
    #pragma unroll 4
    for (int n = 0; n < PP/8; n++) s += base[(size_t)n*FD];
    g_part[blockIdx.x*FD + d] = s;
}

__global__ void k_final(const float* __restrict__ Wl, const float* __restrict__ bl,
                        float* __restrict__ out) {
    int t = threadIdx.x;
    if (t >= BB*CC) return;
    int b = t / CC, c = t % CC;
    float s = 0.f;
    for (int d = 0; d < FD; d++) {
        float p = 0.f;
        #pragma unroll
        for (int q = 0; q < 8; q++) p += g_part[(b*8 + q)*FD + d];
        s = fmaf(p, Wl[d*CC + c], s);
    }
    out[t] = fmaf(s, KINV, bl[c]);
}

// ---------------- launch ----------------

extern "C" void kernel_launch(void* const* d_in, const int* in_sizes, int n_in,
                              void* d_out, int out_size) {
    const float* x  = (const float*)d_in[0];
    const int*   ei = (const int*)  d_in[1];
    const float* W1 = (const float*)d_in[3];
    const float* b1 = (const float*)d_in[4];
    const float* W2 = (const float*)d_in[5];
    const float* b2 = (const float*)d_in[6];
    // d_in[7]=Wa, d_in[8]=ba dead (softmax rows sum to 1); d_in[2]=batch implied
    const float* Wl = (const float*)d_in[9];
    const float* bl = (const float*)d_in[10];
    float* out = (float*)d_out;

    const int E = in_sizes[1] / 2;

    k_splitW    <<<64, 256>>>(W1, W2);
    k_zero      <<<NBLK, 256>>>();
    k_hist      <<<(E + 511)/512, 512>>>(ei, E);
    k_scan_block<<<NBLK, 256>>>();
    k_scan_top  <<<1, 512>>>();
    k_scan_add  <<<NBLK, 256>>>();
    k_fill      <<<(E + 511)/512, 512>>>(ei, E);

    const int gemm_grid   = (NN + 127)/128;
    const int gather_grid = (NN + 7)/8;

    k_gemm_bf<1><<<gemm_grid, 256>>>(x);
    k_gather<1> <<<gather_grid, 256>>>(b1);

    k_gemm_bf<2><<<gemm_grid, 256>>>(x /*unused*/);
    k_gather<2> <<<gather_grid, 256>>>(b2);

    k_pool <<<BB*8, FD>>>();
    k_final<<<1, 512>>>(Wl, bl, out);
}

// round 7
// speedup vs baseline: 1.2118x; 1.2118x over previous
#include <cuda_runtime.h>
#include <cuda_bf16.h>
#include <cstdint>

#define NN 100000
#define EE 1600000
#define FD 128
#define BB 50
#define PP 2000
#define CC 10
#define KINV (1.0f/30.0f)
#define NBLK ((NN + 255) / 256)   // 391

// Scratch (static device globals — no allocation at launch time).
static __device__ uint32_t g_tmpb[NN*64];    // (A@W)*inv as packed bf16x2 (64 u32/row)
static __device__ float    g_h1[NN*FD];      // relu(layer-1 output)
static __device__ float    g_h2[NN*FD];      // relu(layer-2 output)
static __device__ float    g_inv[NN];        // rsqrt(deg+1)
static __device__ float    g_part[BB*8*FD];  // pooling partials
static __device__ int      g_cnt[NN];
static __device__ int      g_cur[NN];
static __device__ int      g_off[NN];
static __device__ int      g_src[EE];
static __device__ int      g_blksum[NBLK];
static __device__ int      g_blkoff[NBLK];

// bf16x2 unpack (exact: bf16 -> f32 is a shift)
__device__ __forceinline__ float bf_lo(uint32_t u) { return __uint_as_float(u << 16); }
__device__ __forceinline__ float bf_hi(uint32_t u) { return __uint_as_float(u & 0xffff0000u); }
__device__ __forceinline__ uint32_t bf_pack(float a, float b) {
    __nv_bfloat162 h = __float22bfloat162_rn(make_float2(a, b));
    return *reinterpret_cast<uint32_t*>(&h);
}

// ---------------- CSR-by-dst construction ----------------

__global__ void k_zero() {
    int i = blockIdx.x*blockDim.x + threadIdx.x;
    if (i < NN) { g_cnt[i] = 0; g_cur[i] = 0; }
}

__global__ void k_hist(const int* __restrict__ ei, int E) {
    int e = blockIdx.x*blockDim.x + threadIdx.x;
    if (e < E) atomicAdd(&g_cnt[ei[E + e]], 1);
}

__global__ void k_scan_block() {
    __shared__ int sh[256];
    int t = threadIdx.x;
    int i = blockIdx.x*256 + t;
    int v = (i < NN) ? g_cnt[i] : 0;
    sh[t] = v;
    __syncthreads();
    #pragma unroll
    for (int d = 1; d < 256; d <<= 1) {
        int x = (t >= d) ? sh[t-d] : 0;
        __syncthreads();
        sh[t] += x;
        __syncthreads();
    }
    if (i < NN) {
        g_off[i] = sh[t] - v;
        g_inv[i] = rsqrtf((float)v + 1.0f);
    }
    if (t == 255) g_blksum[blockIdx.x] = sh[255];
}

__global__ void k_scan_top() {
    __shared__ int sh[512];
    int t = threadIdx.x;
    int v = (t < NBLK) ? g_blksum[t] : 0;
    sh[t] = v;
    __syncthreads();
    #pragma unroll
    for (int d = 1; d < 512; d <<= 1) {
        int x = (t >= d) ? sh[t-d] : 0;
        __syncthreads();
        sh[t] += x;
        __syncthreads();
    }
    if (t < NBLK) g_blkoff[t] = sh[t] - v;
}

__global__ void k_scan_add() {
    int i = blockIdx.x*256 + threadIdx.x;
    if (i < NN) g_off[i] += g_blkoff[blockIdx.x];
}

__global__ void k_fill(const int* __restrict__ ei, int E) {
    int e = blockIdx.x*blockDim.x + threadIdx.x;
    if (e < E) {
        int s = ei[e];
        int d = ei[E + e];
        int pos = g_off[d] + atomicAdd(&g_cur[d], 1);
        g_src[pos] = s;
    }
}

// ---------------- FFMA SGEMM: tmp' = (A @ W) * inv[row], stored bf16x2 ----------------
// Known-good round-3 kernel; only the epilogue changed (bf16x2 packed stores).

template<int LAYER>
__global__ void __launch_bounds__(256)
k_gemm(const float* __restrict__ X, const float* __restrict__ W) {
    const float* A = (LAYER == 1) ? X : (const float*)g_h1;

    __shared__ float As[32][129];   // transposed A chunk: As[kk][row]
    __shared__ float Ws[32][128];   // W chunk: Ws[kk][col]

    const int tid  = threadIdx.x;
    const int row0 = blockIdx.x * 128;
    const int rq   = tid >> 4;
    const int cq   = tid & 15;

    float acc[8][8];
    #pragma unroll
    for (int i = 0; i < 8; i++)
        #pragma unroll
        for (int j = 0; j < 8; j++) acc[i][j] = 0.f;

    for (int k0 = 0; k0 < FD; k0 += 32) {
        #pragma unroll
        for (int i = 0; i < 4; i++) {
            int s  = tid + i*256;
            int r  = s >> 3;
            int kv = s & 7;
            int grow = row0 + r;
            float4 v = make_float4(0.f, 0.f, 0.f, 0.f);
            if (grow < NN)
                v = *reinterpret_cast<const float4*>(A + (size_t)grow*FD + k0 + kv*4);
            As[kv*4+0][r] = v.x; As[kv*4+1][r] = v.y;
            As[kv*4+2][r] = v.z; As[kv*4+3][r] = v.w;
        }
        #pragma unroll
        for (int i = 0; i < 4; i++) {
            int s  = tid + i*256;
            int kk = s >> 5;
            int jv = s & 31;
            *reinterpret_cast<float4*>(&Ws[kk][jv*4]) =
                *reinterpret_cast<const float4*>(W + (size_t)(k0+kk)*FD + jv*4);
        }
        __syncthreads();

        #pragma unroll
        for (int kk = 0; kk < 32; kk++) {
            float a[8], w[8];
            #pragma unroll
            for (int i = 0; i < 8; i++) a[i] = As[kk][rq*8 + i];
            *reinterpret_cast<float4*>(&w[0]) =
                *reinterpret_cast<const float4*>(&Ws[kk][cq*8]);
            *reinterpret_cast<float4*>(&w[4]) =
                *reinterpret_cast<const float4*>(&Ws[kk][cq*8 + 4]);
            #pragma unroll
            for (int i = 0; i < 8; i++)
                #pragma unroll
                for (int j = 0; j < 8; j++)
                    acc[i][j] = fmaf(a[i], w[j], acc[i][j]);
        }
        __syncthreads();
    }

    // Epilogue: pack (acc * inv) into bf16x2
    #pragma unroll
    for (int i = 0; i < 8; i++) {
        int grow = row0 + rq*8 + i;
        if (grow < NN) {
            float iv = g_inv[grow];
            uint4 o;
            o.x = bf_pack(acc[i][0]*iv, acc[i][1]*iv);
            o.y = bf_pack(acc[i][2]*iv, acc[i][3]*iv);
            o.z = bf_pack(acc[i][4]*iv, acc[i][5]*iv);
            o.w = bf_pack(acc[i][6]*iv, acc[i][7]*iv);
            *reinterpret_cast<uint4*>(g_tmpb + (size_t)grow*64 + cq*4) = o;
        }
    }
}

// ---------------- CSR gather (bf16 payload): one warp per dst node ----------------
// H[dst] = relu( inv[dst] * (tmp'[dst] + sum_{src} tmp'[src]) + b )

template<int LAYER>
__global__ void __launch_bounds__(256)
k_gather(const float* __restrict__ bias) {
    int node = blockIdx.x*8 + (threadIdx.x >> 5);
    if (node >= NN) return;
    float* H = (LAYER == 1) ? g_h1 : g_h2;

    const int lane  = threadIdx.x & 31;
    const int start = g_off[node];
    const int deg   = g_cnt[node];

    // self term (4 feats per lane, packed in uint2)
    uint2 sv = *reinterpret_cast<const uint2*>(g_tmpb + (size_t)node*64 + lane*2);
    float4 acc0 = make_float4(bf_lo(sv.x), bf_hi(sv.x), bf_lo(sv.y), bf_hi(sv.y));
    float4 acc1 = make_float4(0.f, 0.f, 0.f, 0.f);

    for (int base = 0; base < deg; base += 32) {
        int n = deg - base; if (n > 32) n = 32;
        int s = (base + lane < deg) ? g_src[start + base + lane] : 0;
        int j = 0;
        for (; j + 1 < n; j += 2) {
            int s0 = __shfl_sync(0xffffffff, s, j);
            int s1 = __shfl_sync(0xffffffff, s, j+1);
            uint2 v0 = *reinterpret_cast<const uint2*>(g_tmpb + (size_t)s0*64 + lane*2);
            uint2 v1 = *reinterpret_cast<const uint2*>(g_tmpb + (size_t)s1*64 + lane*2);
            acc0.x += bf_lo(v0.x); acc0.y += bf_hi(v0.x);
            acc0.z += bf_lo(v0.y); acc0.w += bf_hi(v0.y);
            acc1.x += bf_lo(v1.x); acc1.y += bf_hi(v1.x);
            acc1.z += bf_lo(v1.y); acc1.w += bf_hi(v1.y);
        }
        if (j < n) {
            int s0 = __shfl_sync(0xffffffff, s, j);
            uint2 v0 = *reinterpret_cast<const uint2*>(g_tmpb + (size_t)s0*64 + lane*2);
            acc0.x += bf_lo(v0.x); acc0.y += bf_hi(v0.x);
            acc0.z += bf_lo(v0.y); acc0.w += bf_hi(v0.y);
        }
    }

    float invd = g_inv[node];
    float4 b4 = *reinterpret_cast<const float4*>(bias + lane*4);
    float4 h;
    h.x = fmaxf(fmaf(acc0.x + acc1.x, invd, b4.x), 0.f);
    h.y = fmaxf(fmaf(acc0.y + acc1.y, invd, b4.y), 0.f);
    h.z = fmaxf(fmaf(acc0.z + acc1.z, invd, b4.z), 0.f);
    h.w = fmaxf(fmaf(acc0.w + acc1.w, invd, b4.w), 0.f);
    *reinterpret_cast<float4*>(H + (size_t)node*FD + lane*4) = h;
}

// ---------------- pooling + final ----------------

__global__ void k_pool() {
    int b = blockIdx.x >> 3;
    int q = blockIdx.x & 7;
    int d = threadIdx.x;
    const float* base = g_h2 + ((size_t)(b*PP + q*(PP/8)))*FD + d;
    float s = 0.f;
    #pragma unroll 4
    for (int n = 0; n < PP/8; n++) s += base[(size_t)n*FD];
    g_part[blockIdx.x*FD + d] = s;
}

__global__ void k_final(const float* __restrict__ Wl, const float* __restrict__ bl,
                        float* __restrict__ out) {
    int t = threadIdx.x;
    if (t >= BB*CC) return;
    int b = t / CC, c = t % CC;
    float s = 0.f;
    for (int d = 0; d < FD; d++) {
        float p = 0.f;
        #pragma unroll
        for (int q = 0; q < 8; q++) p += g_part[(b*8 + q)*FD + d];
        s = fmaf(p, Wl[d*CC + c], s);
    }
    out[t] = fmaf(s, KINV, bl[c]);
}

// ---------------- launch ----------------

extern "C" void kernel_launch(void* const* d_in, const int* in_sizes, int n_in,
                              void* d_out, int out_size) {
    const float* x  = (const float*)d_in[0];
    const int*   ei = (const int*)  d_in[1];
    const float* W1 = (const float*)d_in[3];
    const float* b1 = (const float*)d_in[4];
    const float* W2 = (const float*)d_in[5];
    const float* b2 = (const float*)d_in[6];
    // d_in[7]=Wa, d_in[8]=ba dead (softmax rows sum to 1); d_in[2]=batch implied
    const float* Wl = (const float*)d_in[9];
    const float* bl = (const float*)d_in[10];
    float* out = (float*)d_out;

    const int E = in_sizes[1] / 2;

    k_zero      <<<NBLK, 256>>>();
    k_hist      <<<(E + 511)/512, 512>>>(ei, E);
    k_scan_block<<<NBLK, 256>>>();
    k_scan_top  <<<1, 512>>>();
    k_scan_add  <<<NBLK, 256>>>();
    k_fill      <<<(E + 511)/512, 512>>>(ei, E);

    const int gemm_grid   = (NN + 127)/128;
    const int gather_grid = (NN + 7)/8;

    k_gemm<1>  <<<gemm_grid, 256>>>(x, W1);
    k_gather<1><<<gather_grid, 256>>>(b1);

    k_gemm<2>  <<<gemm_grid, 256>>>(x /*unused*/, W2);
    k_gather<2><<<gather_grid, 256>>>(b2);

    k_pool <<<BB*8, FD>>>();
    k_final<<<1, 512>>>(Wl, bl, out);
}